// round 2
// baseline (speedup 1.0000x reference)
#include <cuda_runtime.h>
#include <stdint.h>

#define NB 8
#define HH 96
#define WW 96
#define HW 9216
#define CHW 147456
#define NPIX 73728
#define NPAIR 36864
#define HID 128
#define NSTEPS 64
#define W1COLS 176

typedef unsigned long long ull;

// Scratch (allocation-free)
__device__ float g_bufR[NB * CHW];               // raw (pre-mask) state
__device__ float g_bufM[NB * CHW];               // masked state
__device__ unsigned char g_prelife[NPIX];
__device__ uint32_t g_updbits[NSTEPS * (NPIX / 32)];
__device__ ull g_WzDup[32 * HID];                // (w,w) packed first-layer weights [k][n]
__device__ ull g_W2Dup[HID * 16];                // (w,w) packed second-layer weights [n][c]
__device__ ull g_biasDup[NB * HID];              // (b,b) packed per-batch bias [b][n]

// ---------------- f32x2 helpers ----------------
__device__ __forceinline__ ull fma2(ull a, ull b, ull c) {
  ull d;
  asm("fma.rn.f32x2 %0, %1, %2, %3;" : "=l"(d) : "l"(a), "l"(b), "l"(c));
  return d;
}
__device__ __forceinline__ ull pack2(float lo, float hi) {
  ull r;
  asm("mov.b64 %0, {%1, %2};" : "=l"(r) : "f"(lo), "f"(hi));
  return r;
}
__device__ __forceinline__ float2 unpack2(ull v) {
  float2 f;
  asm("mov.b64 {%0, %1}, %2;" : "=f"(f.x), "=f"(f.y) : "l"(v));
  return f;
}

// ---------------- Threefry-2x32 (matches JAX partitionable) ----------------
__host__ __device__ __forceinline__ void tf2x32(uint32_t k0, uint32_t k1,
                                                uint32_t &x0, uint32_t &x1) {
  uint32_t k2 = k0 ^ k1 ^ 0x1BD11BDAu;
  x0 += k0; x1 += k1;
#define TFR(x, r) x = ((x) << (r)) | ((x) >> (32 - (r)))
#define TFS(r) { x0 += x1; TFR(x1, r); x1 ^= x0; }
  TFS(13) TFS(15) TFS(26) TFS(6)
  x0 += k1; x1 += k2 + 1u;
  TFS(17) TFS(29) TFS(16) TFS(24)
  x0 += k2; x1 += k0 + 2u;
  TFS(13) TFS(15) TFS(26) TFS(6)
  x0 += k0; x1 += k1 + 3u;
  TFS(17) TFS(29) TFS(16) TFS(24)
  x0 += k1; x1 += k2 + 4u;
  TFS(13) TFS(15) TFS(26) TFS(6)
  x0 += k2; x1 += k0 + 5u;
#undef TFS
#undef TFR
}

// ---------------- Precompute: fold + duplicate weights ----------------
__global__ void precompute_kernel(const float* __restrict__ W1,
                                  const float* __restrict__ b1,
                                  const float* __restrict__ W2,
                                  const float* __restrict__ w) {
  int n = threadIdx.x;
  if (n >= HID) return;
  const float* w1row = W1 + n * W1COLS;
  #pragma unroll
  for (int k = 0; k < 16; k++) { float v = w1row[k]; g_WzDup[k * HID + n] = pack2(v, v); }
  #pragma unroll
  for (int c = 0; c < 16; c++) {
    float v = w1row[16 + 2 * c] + w1row[17 + 2 * c];  // fold duplicated sobel outputs
    g_WzDup[(16 + c) * HID + n] = pack2(v, v);
  }
  #pragma unroll
  for (int c = 0; c < 16; c++) { float v = W2[c * HID + n]; g_W2Dup[n * 16 + c] = pack2(v, v); }
  for (int b = 0; b < NB; b++) {
    float acc = b1[n];
    const float* wb = w + b * 128;
    for (int k = 0; k < 128; k++) acc = fmaf(w1row[48 + k], wb[k], acc);
    g_biasDup[b * HID + n] = pack2(acc, acc);
  }
}

// ---------------- Precompute: all 64 steps of threefry update bits ----------------
__global__ void maskgen_kernel() {
  int s = blockIdx.y;
  int j = blockIdx.x * 256 + threadIdx.x;
  uint32_t k0 = 0u, k1 = (uint32_t)s;
  tf2x32(0u, 42u, k0, k1);            // keys[s]
  uint32_t r0 = 0u, r1 = (uint32_t)j;
  tf2x32(k0, k1, r0, r1);
  uint32_t bits = r0 ^ r1;
  uint32_t word = __ballot_sync(0xffffffffu, bits < 0x80000000u);
  if ((threadIdx.x & 31) == 0) g_updbits[s * (NPIX / 32) + (j >> 5)] = word;
}

// ---------------- Step A: perception + packed MLP + stochastic update ----------------
// One thread = two x-adjacent pixels (p0 even), packed into f32x2 lanes.
__global__ void __launch_bounds__(128)
step_a(const float* __restrict__ xext, int use_ext, int stepidx) {
  __shared__ ull sWz[32 * HID];   // 32 KB
  __shared__ ull sW2[HID * 16];   // 16 KB

  {
    const float4* g1 = (const float4*)g_WzDup;
    float4* s1 = (float4*)sWz;
    for (int i = threadIdx.x; i < 32 * HID / 2; i += 128) s1[i] = g1[i];
    const float4* g2 = (const float4*)g_W2Dup;
    float4* s2 = (float4*)sW2;
    for (int i = threadIdx.x; i < HID * 16 / 2; i += 128) s2[i] = g2[i];
  }

  int j2 = blockIdx.x * 128 + threadIdx.x;
  int p0 = j2 * 2;
  int b = p0 / HW;
  int rem = p0 - b * HW;
  int yy = rem / WW;
  int xx = rem - yy * WW;             // even
  const float* __restrict__ src = use_ext ? xext : g_bufM;
  const float* xb = src + b * CHW + rem;
  bool ym = yy > 0, yp = yy < HH - 1, xm = xx > 0, xp = xx < WW - 2;

  ull zz[32];
  float am0 = 0.f, am1 = 0.f;

  // sx channels 0..7 (taps: 3 rows x cols {x-1..x+2})
  #pragma unroll
  for (int c = 0; c < 8; c++) {
    const float* p = xb + c * HW;
    float tm0, tm1, tm2, tm3, t00, t01, t02, t03, tp0, tp1, tp2, tp3;
    float2 cc = *(const float2*)p; t01 = cc.x; t02 = cc.y;
    t00 = xm ? p[-1] : 0.f;
    t03 = xp ? p[2] : 0.f;
    if (ym) { float2 u = *(const float2*)(p - WW); tm1 = u.x; tm2 = u.y;
              tm0 = xm ? p[-WW - 1] : 0.f; tm3 = xp ? p[-WW + 2] : 0.f; }
    else { tm0 = tm1 = tm2 = tm3 = 0.f; }
    if (yp) { float2 u = *(const float2*)(p + WW); tp1 = u.x; tp2 = u.y;
              tp0 = xm ? p[WW - 1] : 0.f; tp3 = xp ? p[WW + 2] : 0.f; }
    else { tp0 = tp1 = tp2 = tp3 = 0.f; }

    zz[c] = pack2(t01, t02);
    float s0 = (tm2 - tm0) + 2.f * (t02 - t00) + (tp2 - tp0);
    float s1 = (tm3 - tm1) + 2.f * (t03 - t01) + (tp3 - tp1);
    zz[16 + c] = pack2(s0, s1);

    if (c == 3) {
      // 3x3 max (valid taps only): px0 cols {x-1,x,x+1}, px1 cols {x,x+1,x+2}
      float m0 = fmaxf(t01, t02);
      float m1 = m0;
      if (xm) m0 = fmaxf(m0, t00);
      if (xp) m1 = fmaxf(m1, t03);
      if (ym) {
        float mm = fmaxf(tm1, tm2);
        m0 = fmaxf(m0, mm); m1 = fmaxf(m1, mm);
        if (xm) m0 = fmaxf(m0, tm0);
        if (xp) m1 = fmaxf(m1, tm3);
      }
      if (yp) {
        float mm = fmaxf(tp1, tp2);
        m0 = fmaxf(m0, mm); m1 = fmaxf(m1, mm);
        if (xm) m0 = fmaxf(m0, tp0);
        if (xp) m1 = fmaxf(m1, tp3);
      }
      am0 = m0; am1 = m1;
    }
  }

  // sy channels 8..15 (taps: rows {y-1,y+1} x cols {x-1..x+2} + centers)
  #pragma unroll
  for (int c = 8; c < 16; c++) {
    const float* p = xb + c * HW;
    float2 cc = *(const float2*)p;
    float tm0, tm1, tm2, tm3, tp0, tp1, tp2, tp3;
    if (ym) { float2 u = *(const float2*)(p - WW); tm1 = u.x; tm2 = u.y;
              tm0 = xm ? p[-WW - 1] : 0.f; tm3 = xp ? p[-WW + 2] : 0.f; }
    else { tm0 = tm1 = tm2 = tm3 = 0.f; }
    if (yp) { float2 u = *(const float2*)(p + WW); tp1 = u.x; tp2 = u.y;
              tp0 = xm ? p[WW - 1] : 0.f; tp3 = xp ? p[WW + 2] : 0.f; }
    else { tp0 = tp1 = tp2 = tp3 = 0.f; }

    zz[c] = pack2(cc.x, cc.y);
    float s0 = (tp0 + 2.f * tp1 + tp2) - (tm0 + 2.f * tm1 + tm2);
    float s1 = (tp1 + 2.f * tp2 + tp3) - (tm1 + 2.f * tm2 + tm3);
    zz[16 + c] = pack2(s0, s1);
  }

  __syncthreads();   // shared weights ready (placed late to overlap fills with sobel loads)

  // MLP: h = relu(Wz^T z + bias); delta = W2 h. All packed over the pixel pair.
  ull acc2[16];
  #pragma unroll
  for (int i = 0; i < 16; i++) acc2[i] = 0ull;

  const ull* bd = g_biasDup + b * HID;
  #pragma unroll 1
  for (int ch = 0; ch < 8; ch++) {
    ull hp[16];
    const ulonglong2* bdv = (const ulonglong2*)(bd + ch * 16);
    #pragma unroll
    for (int i = 0; i < 8; i++) { ulonglong2 v = bdv[i]; hp[2 * i] = v.x; hp[2 * i + 1] = v.y; }

    #pragma unroll
    for (int k = 0; k < 32; k++) {
      const ulonglong2* wv = (const ulonglong2*)(sWz + k * HID + ch * 16);
      ull zk = zz[k];
      #pragma unroll
      for (int i = 0; i < 8; i++) {
        ulonglong2 v = wv[i];
        hp[2 * i]     = fma2(zk, v.x, hp[2 * i]);
        hp[2 * i + 1] = fma2(zk, v.y, hp[2 * i + 1]);
      }
    }

    #pragma unroll
    for (int i = 0; i < 16; i++) {
      float2 h = unpack2(hp[i]);
      h.x = fmaxf(h.x, 0.f); h.y = fmaxf(h.y, 0.f);
      ull hr = pack2(h.x, h.y);
      const ulonglong2* w2v = (const ulonglong2*)(sW2 + (ch * 16 + i) * 16);
      #pragma unroll
      for (int q = 0; q < 8; q++) {
        ulonglong2 v = w2v[q];
        acc2[2 * q]     = fma2(hr, v.x, acc2[2 * q]);
        acc2[2 * q + 1] = fma2(hr, v.y, acc2[2 * q + 1]);
      }
    }
  }

  // Stochastic update mask (precomputed threefry bits) + alpha gate
  uint32_t wbits = g_updbits[stepidx * (NPIX / 32) + (p0 >> 5)];
  float2 a = unpack2(zz[3]);
  int sh = p0 & 31;
  float u0 = (((wbits >> sh) & 1u) && a.x > 0.1f) ? 1.f : 0.f;
  float u1 = (((wbits >> (sh + 1)) & 1u) && a.y > 0.1f) ? 1.f : 0.f;
  ull up = pack2(u0, u1);

  float* ob = g_bufR + b * CHW + rem;
  #pragma unroll
  for (int c = 0; c < 16; c++) {
    ull r = fma2(acc2[c], up, zz[c]);   // x + delta*upd
    *(float2*)(ob + c * HW) = unpack2(r);
  }

  uchar2 pl;
  pl.x = am0 > 0.1f ? 1 : 0;
  pl.y = am1 > 0.1f ? 1 : 0;
  *(uchar2*)(g_prelife + p0) = pl;
}

// ---------------- Step B: alive masking (2 px/thread, float2) ----------------
__global__ void __launch_bounds__(128)
step_b(float* __restrict__ dext, int use_ext) {
  int j2 = blockIdx.x * 128 + threadIdx.x;
  int p0 = j2 * 2;
  int b = p0 / HW;
  int rem = p0 - b * HW;
  int yy = rem / WW;
  int xx = rem - yy * WW;
  const float* rb = g_bufR + b * CHW + rem;
  const float* a = rb + 3 * HW;
  bool ym = yy > 0, yp = yy < HH - 1, xm = xx > 0, xp = xx < WW - 2;

  float2 c0 = *(const float2*)a;
  float m0 = fmaxf(c0.x, c0.y);
  float m1 = m0;
  if (xm) m0 = fmaxf(m0, a[-1]);
  if (xp) m1 = fmaxf(m1, a[2]);
  if (ym) {
    float2 u = *(const float2*)(a - WW);
    float mm = fmaxf(u.x, u.y);
    m0 = fmaxf(m0, mm); m1 = fmaxf(m1, mm);
    if (xm) m0 = fmaxf(m0, a[-WW - 1]);
    if (xp) m1 = fmaxf(m1, a[-WW + 2]);
  }
  if (yp) {
    float2 u = *(const float2*)(a + WW);
    float mm = fmaxf(u.x, u.y);
    m0 = fmaxf(m0, mm); m1 = fmaxf(m1, mm);
    if (xm) m0 = fmaxf(m0, a[WW - 1]);
    if (xp) m1 = fmaxf(m1, a[WW + 2]);
  }

  uchar2 pl = *(const uchar2*)(g_prelife + p0);
  float s0 = (pl.x && m0 > 0.1f) ? 1.f : 0.f;
  float s1 = (pl.y && m1 > 0.1f) ? 1.f : 0.f;

  float* ob = (use_ext ? dext : g_bufM) + b * CHW + rem;
  #pragma unroll
  for (int c = 0; c < 16; c++) {
    float2 v = *(const float2*)(rb + c * HW);
    v.x *= s0; v.y *= s1;
    *(float2*)(ob + c * HW) = v;
  }
}

// ---------------- Host ----------------
extern "C" void kernel_launch(void* const* d_in, const int* in_sizes, int n_in,
                              void* d_out, int out_size) {
  const float* x  = (const float*)d_in[0];
  const float* w  = (const float*)d_in[1];
  const float* W1 = (const float*)d_in[3];
  const float* b1 = (const float*)d_in[4];
  const float* W2 = (const float*)d_in[5];

  precompute_kernel<<<1, HID>>>(W1, b1, W2, w);
  maskgen_kernel<<<dim3(NPIX / 256, NSTEPS), 256>>>();

  const int nblk = NPAIR / 128;   // 288
  for (int s = 0; s < NSTEPS; s++) {
    step_a<<<nblk, 128>>>(x, s == 0 ? 1 : 0, s);
    step_b<<<nblk, 128>>>((float*)d_out, s == NSTEPS - 1 ? 1 : 0);
  }
}

// round 3
// speedup vs baseline: 1.3071x; 1.3071x over previous
#include <cuda_runtime.h>
#include <stdint.h>

#define NB 8
#define HH 96
#define WW 96
#define HW 9216
#define CHW 147456
#define NPIX 73728
#define HID 128
#define NSTEPS 64
#define W1COLS 176

#define TIW 32
#define TIH 8
#define HLW 34
#define HLH 10
#define TSZ 340   // HLW*HLH

typedef unsigned long long ull;

// Scratch (allocation-free)
__device__ float g_R[2][NB * CHW];            // ping-pong raw (pre-mask) state
__device__ unsigned char g_PL[2][NPIX];       // ping-pong prelife
__device__ uint32_t g_updbits[NSTEPS * (NPIX / 32)];
__device__ float g_Wz[32 * HID];              // folded layer-1 weights [k][n]
__device__ ull g_W2p[64 * 16];                // layer-2 weights, lane-paired (even n, odd n) [pair][c]
__device__ ull g_biasP[NB * 64];              // per-batch bias pairs [b][pair]

// ---------------- f32x2 helpers ----------------
__device__ __forceinline__ ull fma2(ull a, ull b, ull c) {
  ull d;
  asm("fma.rn.f32x2 %0, %1, %2, %3;" : "=l"(d) : "l"(a), "l"(b), "l"(c));
  return d;
}
__device__ __forceinline__ ull pack2(float lo, float hi) {
  ull r;
  asm("mov.b64 %0, {%1, %2};" : "=l"(r) : "f"(lo), "f"(hi));
  return r;
}
__device__ __forceinline__ float2 unpack2(ull v) {
  float2 f;
  asm("mov.b64 {%0, %1}, %2;" : "=f"(f.x), "=f"(f.y) : "l"(v));
  return f;
}

// ---------------- Threefry-2x32 (matches JAX partitionable) ----------------
__device__ __forceinline__ void tf2x32(uint32_t k0, uint32_t k1,
                                       uint32_t &x0, uint32_t &x1) {
  uint32_t k2 = k0 ^ k1 ^ 0x1BD11BDAu;
  x0 += k0; x1 += k1;
#define TFR(x, r) x = ((x) << (r)) | ((x) >> (32 - (r)))
#define TFS(r) { x0 += x1; TFR(x1, r); x1 ^= x0; }
  TFS(13) TFS(15) TFS(26) TFS(6)
  x0 += k1; x1 += k2 + 1u;
  TFS(17) TFS(29) TFS(16) TFS(24)
  x0 += k2; x1 += k0 + 2u;
  TFS(13) TFS(15) TFS(26) TFS(6)
  x0 += k0; x1 += k1 + 3u;
  TFS(17) TFS(29) TFS(16) TFS(24)
  x0 += k1; x1 += k2 + 4u;
  TFS(13) TFS(15) TFS(26) TFS(6)
  x0 += k2; x1 += k0 + 5u;
#undef TFS
#undef TFR
}

// ---------------- Precompute weights ----------------
__global__ void precompute_kernel(const float* __restrict__ W1,
                                  const float* __restrict__ b1,
                                  const float* __restrict__ W2,
                                  const float* __restrict__ w) {
  __shared__ float sb[NB][HID];
  int n = threadIdx.x;
  if (n >= HID) return;
  const float* w1row = W1 + n * W1COLS;
  #pragma unroll
  for (int k = 0; k < 16; k++) g_Wz[k * HID + n] = w1row[k];
  #pragma unroll
  for (int c = 0; c < 16; c++)
    g_Wz[(16 + c) * HID + n] = w1row[16 + 2 * c] + w1row[17 + 2 * c];
  for (int b = 0; b < NB; b++) {
    float acc = b1[n];
    const float* wb = w + b * 128;
    for (int k = 0; k < 128; k++) acc = fmaf(w1row[48 + k], wb[k], acc);
    sb[b][n] = acc;
  }
  __syncthreads();
  if (!(n & 1)) {
    int p = n >> 1;
    #pragma unroll
    for (int c = 0; c < 16; c++)
      g_W2p[p * 16 + c] = pack2(W2[c * HID + n], W2[c * HID + n + 1]);
    for (int b = 0; b < NB; b++)
      g_biasP[b * 64 + p] = pack2(sb[b][n], sb[b][n + 1]);
  }
}

// ---------------- Precompute threefry update bits for all steps ----------------
__global__ void maskgen_kernel() {
  int s = blockIdx.y;
  int j = blockIdx.x * 256 + threadIdx.x;
  uint32_t k0 = 0u, k1 = (uint32_t)s;
  tf2x32(0u, 42u, k0, k1);            // keys[s]
  uint32_t r0 = 0u, r1 = (uint32_t)j;
  tf2x32(k0, k1, r0, r1);
  uint32_t bits = r0 ^ r1;
  uint32_t word = __ballot_sync(0xffffffffu, bits < 0x80000000u);
  if ((threadIdx.x & 31) == 0) g_updbits[s * (NPIX / 32) + (j >> 5)] = word;
}

// ---------------- Fused step: life mask + perception + MLP + update ----------------
__global__ void __launch_bounds__(256, 2)
step_f(const float* __restrict__ xext, int s) {
  __shared__ __align__(16) float sWz[32 * HID];   // 16KB (first 1728B aliased as alpha halo2)
  __shared__ __align__(16) ull sW2p[64 * 16];     // 8KB
  __shared__ __align__(16) ull sbiasP[64];        // 512B
  __shared__ __align__(16) float smx[16 * TSZ];   // masked tile (0 OOB), 21.25KB
  __shared__ float salive[TSZ];                   // masked alpha, -inf OOB
  __shared__ unsigned char slife[TSZ];

  int tid = threadIdx.x;
  int blk = blockIdx.x;
  int b   = blk / 36;
  int t   = blk - b * 36;
  int tx0 = (t % 3) * TIW;
  int ty0 = (t / 3) * TIH;

  const float* __restrict__ Rin = g_R[(s + 1) & 1] + b * CHW;
  const unsigned char* __restrict__ PLin = g_PL[(s + 1) & 1] + b * HW;

  // Phase 1 (s>0): compute life mask on halo1 region from prev raw alpha + prelife
  if (s > 0) {
    float* salpha2 = sWz;   // alias: dead before weights load
    for (int r = tid; r < 432; r += 256) {
      int ay = r / 36, ax = r - (r / 36) * 36;
      int gy = ty0 + ay - 2, gx = tx0 + ax - 2;
      bool in = (unsigned)gy < 96u && (unsigned)gx < 96u;
      salpha2[r] = in ? __ldg(Rin + 3 * HW + gy * WW + gx) : -1e30f;
    }
    __syncthreads();
    for (int r = tid; r < TSZ; r += 256) {
      int ly = r / HLW, lx = r - (r / HLW) * HLW;
      int gy = ty0 + ly - 1, gx = tx0 + lx - 1;
      bool in = (unsigned)gy < 96u && (unsigned)gx < 96u;
      float m = -1e30f;
      #pragma unroll
      for (int dy = 0; dy < 3; dy++) {
        const float* row = salpha2 + (ly + dy) * 36 + lx;
        m = fmaxf(m, row[0]);
        m = fmaxf(m, row[1]);
        m = fmaxf(m, row[2]);
      }
      unsigned char lf = 0;
      if (in && m > 0.1f && PLin[gy * WW + gx]) lf = 1;
      slife[r] = lf;
    }
    __syncthreads();    // salpha2 dead after this point
  }

  // Phase 2: load weights (overwrites salpha2 alias) + masked tile
  {
    const float4* g1 = (const float4*)g_Wz;
    float4* s1 = (float4*)sWz;
    #pragma unroll
    for (int i = tid; i < 32 * HID / 4; i += 256) s1[i] = g1[i];
    const float4* g2 = (const float4*)g_W2p;
    float4* s2 = (float4*)sW2p;
    #pragma unroll
    for (int i = tid; i < 512; i += 256) s2[i] = g2[i];
    if (tid < 64) sbiasP[tid] = g_biasP[b * 64 + tid];
  }
  if (s == 0) {
    const float* xb = xext + b * CHW;
    for (int e = tid; e < 16 * TSZ; e += 256) {
      int c = e / TSZ, r = e - (e / TSZ) * TSZ;
      int ly = r / HLW, lx = r - (r / HLW) * HLW;
      int gy = ty0 + ly - 1, gx = tx0 + lx - 1;
      bool in = (unsigned)gy < 96u && (unsigned)gx < 96u;
      float v = in ? __ldg(xb + c * HW + gy * WW + gx) : 0.f;
      smx[e] = v;
      if (c == 3) salive[r] = in ? v : -1e30f;
    }
  } else {
    for (int e = tid; e < 16 * TSZ; e += 256) {
      int c = e / TSZ, r = e - (e / TSZ) * TSZ;
      int ly = r / HLW, lx = r - (r / HLW) * HLW;
      int gy = ty0 + ly - 1, gx = tx0 + lx - 1;
      bool in = (unsigned)gy < 96u && (unsigned)gx < 96u;
      float v = (in && slife[r]) ? __ldg(Rin + c * HW + gy * WW + gx) : 0.f;
      smx[e] = v;
      if (c == 3) salive[r] = in ? v : -1e30f;
    }
  }
  __syncthreads();

  // Phase 3: per-pixel compute
  int px = tid & 31, py = tid >> 5;
  int ctr = (py + 1) * HLW + (px + 1);

  float z[32];
  #pragma unroll
  for (int c = 0; c < 16; c++) z[c] = smx[c * TSZ + ctr];
  #pragma unroll
  for (int c = 0; c < 8; c++) {       // sx
    const float* a = smx + c * TSZ;
    z[16 + c] = (a[ctr - HLW + 1] - a[ctr - HLW - 1])
              + 2.f * (a[ctr + 1] - a[ctr - 1])
              + (a[ctr + HLW + 1] - a[ctr + HLW - 1]);
  }
  #pragma unroll
  for (int c = 8; c < 16; c++) {      // sy
    const float* a = smx + c * TSZ;
    z[16 + c] = (a[ctr + HLW - 1] - a[ctr - HLW - 1])
              + 2.f * (a[ctr + HLW] - a[ctr - HLW])
              + (a[ctr + HLW + 1] - a[ctr - HLW + 1]);
  }

  // pre_life: 3x3 max over masked alpha (-inf OOB pads)
  float m = salive[ctr];
  m = fmaxf(m, salive[ctr - 1]);
  m = fmaxf(m, salive[ctr + 1]);
  m = fmaxf(m, salive[ctr - HLW - 1]);
  m = fmaxf(m, salive[ctr - HLW]);
  m = fmaxf(m, salive[ctr - HLW + 1]);
  m = fmaxf(m, salive[ctr + HLW - 1]);
  m = fmaxf(m, salive[ctr + HLW]);
  m = fmaxf(m, salive[ctr + HLW + 1]);

  // MLP: h = relu(Wz^T z + bias); delta = W2 h. Hidden units lane-paired in f32x2.
  ull acc2[16];
  #pragma unroll
  for (int i = 0; i < 16; i++) acc2[i] = 0ull;

  #pragma unroll 1
  for (int gc = 0; gc < 8; gc++) {      // 16 hidden units (8 pairs) per chunk
    ull h[8];
    {
      const ulonglong2* bb = (const ulonglong2*)(sbiasP + gc * 8);
      #pragma unroll
      for (int i = 0; i < 4; i++) { ulonglong2 v = bb[i]; h[2 * i] = v.x; h[2 * i + 1] = v.y; }
    }
    #pragma unroll
    for (int k = 0; k < 32; k++) {
      ull zkk = pack2(z[k], z[k]);
      const ulonglong2* wv = (const ulonglong2*)(sWz + k * HID + gc * 16);
      #pragma unroll
      for (int i = 0; i < 4; i++) {
        ulonglong2 v = wv[i];
        h[2 * i]     = fma2(zkk, v.x, h[2 * i]);
        h[2 * i + 1] = fma2(zkk, v.y, h[2 * i + 1]);
      }
    }
    #pragma unroll
    for (int p = 0; p < 8; p++) {
      float2 hf = unpack2(h[p]);
      ull hr = pack2(fmaxf(hf.x, 0.f), fmaxf(hf.y, 0.f));
      const ulonglong2* w2 = (const ulonglong2*)(sW2p + (gc * 8 + p) * 16);
      #pragma unroll
      for (int q = 0; q < 8; q++) {
        ulonglong2 v = w2[q];
        acc2[2 * q]     = fma2(hr, v.x, acc2[2 * q]);
        acc2[2 * q + 1] = fma2(hr, v.y, acc2[2 * q + 1]);
      }
    }
  }

  // Stochastic update gate
  int gy = ty0 + py, gx = tx0 + px;
  int j = b * HW + gy * WW + gx;
  uint32_t wbits = g_updbits[s * (NPIX / 32) + (j >> 5)];
  float u = (((wbits >> (j & 31)) & 1u) && z[3] > 0.1f) ? 1.f : 0.f;

  float* Rout = g_R[s & 1] + b * CHW + gy * WW + gx;
  #pragma unroll
  for (int c = 0; c < 16; c++) {
    float2 f = unpack2(acc2[c]);
    Rout[c * HW] = fmaf(f.x + f.y, u, z[c]);
  }
  g_PL[s & 1][j] = m > 0.1f ? 1 : 0;
}

// ---------------- Final alive masking -> d_out ----------------
__global__ void __launch_bounds__(256)
final_mask(float* __restrict__ dout) {
  const float* __restrict__ R = g_R[(NSTEPS - 1) & 1];
  const unsigned char* __restrict__ PL = g_PL[(NSTEPS - 1) & 1];

  int j = blockIdx.x * 256 + threadIdx.x;
  int b = j / HW;
  int rem = j - b * HW;
  int yy = rem / WW;
  int xx = rem - yy * WW;
  const float* rb = R + b * CHW + rem;
  const float* a = rb + 3 * HW;
  bool ym = yy > 0, yp = yy < HH - 1, xm = xx > 0, xp = xx < WW - 1;

  float m = __ldg(a);
  if (ym) {
    m = fmaxf(m, __ldg(a - WW));
    if (xm) m = fmaxf(m, __ldg(a - WW - 1));
    if (xp) m = fmaxf(m, __ldg(a - WW + 1));
  }
  if (xm) m = fmaxf(m, __ldg(a - 1));
  if (xp) m = fmaxf(m, __ldg(a + 1));
  if (yp) {
    m = fmaxf(m, __ldg(a + WW));
    if (xm) m = fmaxf(m, __ldg(a + WW - 1));
    if (xp) m = fmaxf(m, __ldg(a + WW + 1));
  }
  float sc = (PL[j] && m > 0.1f) ? 1.f : 0.f;

  float* ob = dout + b * CHW + rem;
  #pragma unroll
  for (int c = 0; c < 16; c++) ob[c * HW] = __ldg(rb + c * HW) * sc;
}

// ---------------- Host ----------------
extern "C" void kernel_launch(void* const* d_in, const int* in_sizes, int n_in,
                              void* d_out, int out_size) {
  const float* x  = (const float*)d_in[0];
  const float* w  = (const float*)d_in[1];
  const float* W1 = (const float*)d_in[3];
  const float* b1 = (const float*)d_in[4];
  const float* W2 = (const float*)d_in[5];

  precompute_kernel<<<1, HID>>>(W1, b1, W2, w);
  maskgen_kernel<<<dim3(NPIX / 256, NSTEPS), 256>>>();

  for (int s = 0; s < NSTEPS; s++)
    step_f<<<NB * 36, 256>>>(x, s);

  final_mask<<<NPIX / 256, 256>>>((float*)d_out);
}